// round 15
// baseline (speedup 1.0000x reference)
#include <cuda_runtime.h>
#include <cuda_fp16.h>
#include <cstdint>

// ---------------------------------------------------------------------------
// SelfAttention B=4, T=2048, D=1024, causal — fp16 persistent edition v5.
// R14 (303.5us) + PV load-balance fix:
//   * dynamic ticket scheduling for PV (work per tile ~ by+1 was 3.3x skewed;
//     static striding left a 46-kt straggler CTA vs 29.4-kt average)
//   * per-(row,tile) softmax scales precomputed in a tiny kernel ->
//     PV prologue is a coalesced copy (no serial expf / uncoalesced loads)
//   Proj: Q = Xh Wq^T / 32 ; K = Xh Wk^T ; Vt = (Xh Wv^T)^T   (fp16 outputs)
//   S-GEMM (live causal tiles): P_t = exp(S - m_tile) (fp16) + (m,l) partials
//   PV-GEMM: A fragments scaled via __hmul2. out(f32) = softmax(S) V.
// GEMM core: 128x128x(BK=64 fp16), 3-stage cp.async, XOR-swizzled smem,
// ldmatrix.x4.b16, m16n8k16 (f32 acc), 8 warps, 2 CTAs/SM, persistent 296.
// ---------------------------------------------------------------------------

namespace {
constexpr int BATCH = 4;
constexpr int T     = 2048;
constexpr int D     = 1024;
constexpr int MQKV  = BATCH * T;          // 8192
constexpr int NTILE = T / 128;            // 16

constexpr int BM = 128, BN = 128, BK = 64;   // BK fp16 = 128 B rows
constexpr int STG = 3;
constexpr int NT  = 256;                      // 8 warps
constexpr int GRID_P = 296;                   // persistent CTAs

constexpr int A_STG = BM * 128;               // 16384 B
constexpr int B_STG = BN * 128;               // 16384 B
constexpr int STG_BYTES = A_STG + B_STG;      // 32768 B
constexpr int SMEM_TOTAL = STG * STG_BYTES;   // 98304 B

constexpr int NT_S  = BATCH * (NTILE * (NTILE + 1) / 2);  // 544
constexpr int NT_PV = (D / BN) * NTILE * BATCH;           // 512
constexpr int NT_PJ = (D / BN) * (MQKV / BM) * 3;         // 1536

constexpr int TSTRIDE = 130;                  // transpose buffer stride (halves)

constexpr int NX4 = MQKV * D / 4;             // 2097152
constexpr int NW4 = D * D / 4;                // 262144
constexpr int NALL4 = NX4 + 3 * NW4;          // 2883584
}

// scratch (device globals — allocation-free)
__device__ __half g_Xh[(size_t)MQKV * D];
__device__ __half g_Wq[(size_t)D * D];
__device__ __half g_Wk[(size_t)D * D];
__device__ __half g_Wv[(size_t)D * D];
__device__ __half g_Q [(size_t)MQKV * D];
__device__ __half g_K [(size_t)MQKV * D];
__device__ __half g_Vt[(size_t)D * MQKV];                 // V transposed [D][B*T]
__device__ __half g_S [(size_t)BATCH * T * T];            // P_t (fp16)
__device__ float  g_pm[(size_t)BATCH * T * NTILE];
__device__ float  g_pl[(size_t)BATCH * T * NTILE];
__device__ float  g_scale[(size_t)BATCH * NTILE * T];     // [b][tile][row]
__device__ int    g_ticket;                               // PV dynamic scheduler

// ---------------------------------------------------------------------------
// helpers
// ---------------------------------------------------------------------------
__device__ __forceinline__ uint32_t smem_u32(const void* p) {
    uint32_t a;
    asm("{ .reg .u64 t; cvta.to.shared.u64 t, %1; cvt.u32.u64 %0, t; }" : "=r"(a) : "l"(p));
    return a;
}
__device__ __forceinline__ void cp16s(uint32_t s, const void* g) {
    asm volatile("cp.async.cg.shared.global [%0], [%1], 16;" ::"r"(s), "l"(g));
}
__device__ __forceinline__ void cp_commit() { asm volatile("cp.async.commit_group;"); }
__device__ __forceinline__ void cp_wait1()  { asm volatile("cp.async.wait_group 1;"); }

__device__ __forceinline__ void ldsm4(uint32_t& r0, uint32_t& r1, uint32_t& r2,
                                      uint32_t& r3, uint32_t addr) {
    asm volatile("ldmatrix.sync.aligned.m8n8.x4.shared.b16 {%0,%1,%2,%3}, [%4];"
                 : "=r"(r0), "=r"(r1), "=r"(r2), "=r"(r3) : "r"(addr));
}
__device__ __forceinline__ void mma16(float* c, const uint32_t* a, const uint32_t* b) {
    asm volatile(
        "mma.sync.aligned.m16n8k16.row.col.f32.f16.f16.f32 "
        "{%0,%1,%2,%3}, {%4,%5,%6,%7}, {%8,%9}, {%0,%1,%2,%3};"
        : "+f"(c[0]), "+f"(c[1]), "+f"(c[2]), "+f"(c[3])
        : "r"(a[0]), "r"(a[1]), "r"(a[2]), "r"(a[3]), "r"(b[0]), "r"(b[1]));
}
__device__ __forceinline__ uint32_t hmul2u(uint32_t a, __half2 s) {
    __half2 h = *reinterpret_cast<__half2*>(&a);
    h = __hmul2(h, s);
    return *reinterpret_cast<uint32_t*>(&h);
}

// ---------------------------------------------------------------------------
// Persistent TN GEMM (fp16 operands, f32 acc):  C[m,n] = sum_k A[m,k] B[n,k]
//   MODE 0: S = QK^T over live causal tiles (static); exp+partials epilogue
//   MODE 1: out = softmax(S) V; DYNAMIC ticket, heavy-first; hmul2 scaling
//   MODE 2: QKV projection (static); bz==2 -> Vt via smem-staged transpose
// ---------------------------------------------------------------------------
template <int MODE>
__global__ void __launch_bounds__(NT, 2)
tc_gemm(const __half* __restrict__ A,
        const __half* __restrict__ B0, const __half* __restrict__ B1,
        const __half* __restrict__ B2,
        void* __restrict__ C0, void* __restrict__ C1, void* __restrict__ C2,
        float* __restrict__ pm, float* __restrict__ pl,
        const float* __restrict__ scl,
        int Kbase, int lda, int ldb, int ldc,
        long long sA, long long sB, long long sC) {
    extern __shared__ char smem[];
    const uint32_t sb = smem_u32(smem);
    __shared__ float red[4 * 128];               // MODE 0 reductions
    __shared__ float srow[128];
    __shared__ float saux[NTILE * 128];          // MODE 1 scale table
    __shared__ int   s_tile;                     // MODE 1 ticket broadcast

    const int tid = threadIdx.x, w = tid >> 5, lane = tid & 31;
    const int wm = w >> 2, wn = w & 3;           // 2 x 4 warps, 64x32 each

    const int cr = tid >> 3, cc = tid & 7;
    const uint32_t c_sw = (uint32_t)(cc * 16) ^ ((uint32_t)(cr & 7) << 4);

    const int l7 = lane & 7, lb3 = (lane >> 3) & 1, lb4 = (lane >> 4) & 1;
    const uint32_t xr = (uint32_t)l7 << 4;
    const uint32_t aRow0 = (uint32_t)(wm * 64 + lb3 * 8 + l7) * 128;
    const uint32_t aSeg  = (uint32_t)lb4 * 16;
    const uint32_t bRow0 = (uint32_t)(wn * 32 + lb4 * 8 + l7) * 128;
    const uint32_t bSeg  = (uint32_t)lb3 * 16;

    const int ntiles = (MODE == 0) ? NT_S : (MODE == 1) ? NT_PV : NT_PJ;

    const __half* Ab = nullptr;
    const __half* Bb = nullptr;

    auto ldst = [&](int slot, int kt) {
        const uint32_t stg = sb + slot * STG_BYTES;
        const __half* ag = Ab + kt * BK;
#pragma unroll
        for (int i = 0; i < 4; i++) {
            int r = cr + i * 32;
            cp16s(stg + (uint32_t)r * 128 + c_sw, ag + (size_t)r * lda + cc * 8);
        }
        const __half* bg = Bb + kt * BK;
#pragma unroll
        for (int i = 0; i < 4; i++) {
            int r = cr + i * 32;
            cp16s(stg + A_STG + (uint32_t)r * 128 + c_sw, bg + (size_t)r * ldb + cc * 8);
        }
    };

    int t = blockIdx.x;                          // static modes
    while (true) {
        if (MODE == 1) {
            __syncthreads();                     // protect s_tile / saux reuse
            if (tid == 0) s_tile = atomicAdd(&g_ticket, 1);
            __syncthreads();
            t = s_tile;
        }
        if (t >= ntiles) break;

        // ---- decode tile ----
        int bx, by, bz;
        if (MODE == 0) {
            bz = t / (NT_S / BATCH);
            int i0 = t % (NT_S / BATCH);
            int acc0 = 0; by = 0;
            while (i0 >= acc0 + by + 1) { acc0 += by + 1; by++; }
            bx = i0 - acc0;
        } else if (MODE == 1) {
            by = (NTILE - 1) - (t >> 5);         // heavy first
            int r = t & 31; bx = r & 7; bz = r >> 3;
        } else {
            bz = t >> 9; int r = t & 511; by = r >> 3; bx = r & 7;
        }

        const int K = (MODE == 1) ? (by + 1) * BM : Kbase;
        const int nkt = K / BK;

        const __half* Bsel = (MODE == 2) ? (bz == 0 ? B0 : bz == 1 ? B1 : B2) : B0;
        Ab = A + (size_t)bz * sA + (size_t)by * BM * lda;
        Bb = Bsel + (size_t)bz * sB + (size_t)bx * BN * ldb;

        ldst(0, 0); cp_commit();
        if (nkt > 1) ldst(1, 1);
        cp_commit();

        if (MODE == 1) {
            // coalesced copy of precomputed scales: saux[tx*128+row]
            const float* gs = scl + ((size_t)bz * NTILE) * T + (size_t)by * BM;
            const int ne = (by + 1) * 128;
            for (int e = tid; e < ne; e += NT) {
                const int tx = e >> 7, row = e & 127;
                saux[e] = gs[(size_t)tx * T + row];
            }
            __syncthreads();
        }

        float acc[4][4][4];
#pragma unroll
        for (int i = 0; i < 4; i++)
#pragma unroll
            for (int j = 0; j < 4; j++)
#pragma unroll
                for (int k = 0; k < 4; k++) acc[i][j][k] = 0.f;

        __half2 sc0[4], sc1[4];
        int slot = 0;
        for (int kt = 0; kt < nkt; kt++) {
            cp_wait1();
            __syncthreads();                      // single per-kt barrier
            if (kt + 2 < nkt) {
                int ns = slot + 2; if (ns >= STG) ns -= STG;
                ldst(ns, kt + 2);
            }
            cp_commit();

            if (MODE == 1 && (kt & 1) == 0) {
                const int tx = kt >> 1;
#pragma unroll
                for (int mi = 0; mi < 4; mi++) {
                    const int ar = wm * 64 + mi * 16 + (lane >> 2);
                    sc0[mi] = __float2half2_rn(saux[tx * 128 + ar]);
                    sc1[mi] = __float2half2_rn(saux[tx * 128 + ar + 8]);
                }
            }

            const uint32_t astg = sb + slot * STG_BYTES;
            const uint32_t bstg = astg + A_STG;
#pragma unroll
            for (int kk4 = 0; kk4 < 128; kk4 += 32) {
                uint32_t af[4][4], bf[4][2];
                const uint32_t aoff = ((uint32_t)kk4 | aSeg) ^ xr;
                const uint32_t boff = ((uint32_t)kk4 | bSeg) ^ xr;
#pragma unroll
                for (int mi = 0; mi < 4; mi++) {
                    ldsm4(af[mi][0], af[mi][1], af[mi][2], af[mi][3],
                          astg + aRow0 + (uint32_t)mi * 2048 + aoff);
                    if (MODE == 1) {
                        af[mi][0] = hmul2u(af[mi][0], sc0[mi]);
                        af[mi][2] = hmul2u(af[mi][2], sc0[mi]);
                        af[mi][1] = hmul2u(af[mi][1], sc1[mi]);
                        af[mi][3] = hmul2u(af[mi][3], sc1[mi]);
                    }
                }
#pragma unroll
                for (int nj = 0; nj < 2; nj++) {
                    uint32_t r0, r1, r2, r3;
                    ldsm4(r0, r1, r2, r3, bstg + bRow0 + (uint32_t)nj * 2048 + boff);
                    bf[nj * 2][0] = r0; bf[nj * 2][1] = r1;
                    bf[nj * 2 + 1][0] = r2; bf[nj * 2 + 1][1] = r3;
                }
#pragma unroll
                for (int mi = 0; mi < 4; mi++)
#pragma unroll
                    for (int ni = 0; ni < 4; ni++) mma16(acc[mi][ni], af[mi], bf[ni]);
            }
            if (++slot == STG) slot = 0;
        }
        __syncthreads();                          // all compute done; smem free

        // ---- MODE 0 epilogue: exp + stats ----
        if (MODE == 0) {
            const bool diag = (bx == by);
#pragma unroll
            for (int mi = 0; mi < 4; mi++) {
#pragma unroll
                for (int h = 0; h < 2; h++) {
                    const int r = wm * 64 + mi * 16 + (lane >> 2) + 8 * h;
                    float mx = -3.4e38f;
#pragma unroll
                    for (int ni = 0; ni < 4; ni++) {
#pragma unroll
                        for (int c2 = 0; c2 < 2; c2++) {
                            const int c = wn * 32 + ni * 8 + ((lane & 3) << 1) + c2;
                            const bool ok = !diag || (c <= r);
                            if (ok) mx = fmaxf(mx, acc[mi][ni][2 * h + c2]);
                        }
                    }
                    mx = fmaxf(mx, __shfl_xor_sync(0xffffffffu, mx, 1));
                    mx = fmaxf(mx, __shfl_xor_sync(0xffffffffu, mx, 2));
                    if ((lane & 3) == 0) red[wn * 128 + r] = mx;
                }
            }
            __syncthreads();
            if (tid < 128)
                srow[tid] = fmaxf(fmaxf(red[tid], red[128 + tid]),
                                  fmaxf(red[256 + tid], red[384 + tid]));
            __syncthreads();
#pragma unroll
            for (int mi = 0; mi < 4; mi++) {
#pragma unroll
                for (int h = 0; h < 2; h++) {
                    const int r = wm * 64 + mi * 16 + (lane >> 2) + 8 * h;
                    const float m = srow[r];
                    float sum = 0.f;
#pragma unroll
                    for (int ni = 0; ni < 4; ni++) {
#pragma unroll
                        for (int c2 = 0; c2 < 2; c2++) {
                            const int c = wn * 32 + ni * 8 + ((lane & 3) << 1) + c2;
                            const bool ok = !diag || (c <= r);
                            const float e = ok ? __expf(acc[mi][ni][2 * h + c2] - m) : 0.f;
                            acc[mi][ni][2 * h + c2] = e;
                            sum += e;
                        }
                    }
                    sum += __shfl_xor_sync(0xffffffffu, sum, 1);
                    sum += __shfl_xor_sync(0xffffffffu, sum, 2);
                    if ((lane & 3) == 0) red[wn * 128 + r] = sum;
                }
            }
            __syncthreads();
            if (tid < 128) {
                const float l = red[tid] + red[128 + tid] + red[256 + tid] + red[384 + tid];
                const int q = by * BM + tid;
                pm[((size_t)bz * T + q) * NTILE + bx] = srow[tid];
                pl[((size_t)bz * T + q) * NTILE + bx] = l;
            }
            __syncthreads();
        }

        // ---- store ----
        if (MODE == 2 && bz == 2) {
            __half* sT = reinterpret_cast<__half*>(smem);
#pragma unroll
            for (int mi = 0; mi < 4; mi++) {
#pragma unroll
                for (int ni = 0; ni < 4; ni++) {
                    const int r0 = wm * 64 + mi * 16 + (lane >> 2);
                    const int c0 = wn * 32 + ni * 8 + ((lane & 3) << 1);
                    sT[c0 * TSTRIDE + r0]           = __float2half_rn(acc[mi][ni][0]);
                    sT[(c0 + 1) * TSTRIDE + r0]     = __float2half_rn(acc[mi][ni][1]);
                    sT[c0 * TSTRIDE + r0 + 8]       = __float2half_rn(acc[mi][ni][2]);
                    sT[(c0 + 1) * TSTRIDE + r0 + 8] = __float2half_rn(acc[mi][ni][3]);
                }
            }
            __syncthreads();
            __half* Cv = (__half*)C2;
            const int gr0 = by * BM;
#pragma unroll
            for (int i = 0; i < 32; i++) {
                const int idx = tid + i * NT;
                const int c  = idx >> 6;
                const int rp = idx & 63;
                const __half2 hv = *reinterpret_cast<const __half2*>(
                    &sT[c * TSTRIDE + rp * 2]);
                *reinterpret_cast<__half2*>(
                    &Cv[(size_t)(bx * BN + c) * MQKV + gr0 + rp * 2]) = hv;
            }
            __syncthreads();
        } else {
#pragma unroll
            for (int mi = 0; mi < 4; mi++) {
#pragma unroll
                for (int ni = 0; ni < 4; ni++) {
                    const int row = by * BM + wm * 64 + mi * 16 + (lane >> 2);
                    const int col = bx * BN + wn * 32 + ni * 8 + ((lane & 3) << 1);
                    float v0 = acc[mi][ni][0], v1 = acc[mi][ni][1];
                    float v2 = acc[mi][ni][2], v3 = acc[mi][ni][3];
                    if (MODE == 2) {
                        if (bz == 0) { v0 *= 0.03125f; v1 *= 0.03125f; v2 *= 0.03125f; v3 *= 0.03125f; }
                        __half* Cd = (__half*)(bz == 0 ? C0 : C1);
                        *reinterpret_cast<__half2*>(Cd + (size_t)row * ldc + col) =
                            __floats2half2_rn(v0, v1);
                        *reinterpret_cast<__half2*>(Cd + (size_t)(row + 8) * ldc + col) =
                            __floats2half2_rn(v2, v3);
                    } else if (MODE == 0) {
                        __half* Cd = (__half*)C0 + (size_t)bz * sC;
                        *reinterpret_cast<__half2*>(Cd + (size_t)row * ldc + col) =
                            __floats2half2_rn(v0, v1);
                        *reinterpret_cast<__half2*>(Cd + (size_t)(row + 8) * ldc + col) =
                            __floats2half2_rn(v2, v3);
                    } else {
                        float* Cd = (float*)C0 + (size_t)bz * sC;
                        *reinterpret_cast<float2*>(Cd + (size_t)row * ldc + col) = make_float2(v0, v1);
                        *reinterpret_cast<float2*>(Cd + (size_t)(row + 8) * ldc + col) = make_float2(v2, v3);
                    }
                }
            }
        }
        if (MODE != 1) {
            t += gridDim.x;
            if (t >= ntiles) break;
        }
    }
}

// ---------------------------------------------------------------------------
// merged elementwise fp32 -> fp16 conversion for X, Wq, Wk, Wv (one launch)
// ---------------------------------------------------------------------------
__global__ void __launch_bounds__(256)
cvt_all_kernel(const float* __restrict__ X,  const float* __restrict__ Wq,
               const float* __restrict__ Wk, const float* __restrict__ Wv,
               __half* __restrict__ Xh,  __half* __restrict__ Wqh,
               __half* __restrict__ Wkh, __half* __restrict__ Wvh) {
    int i = blockIdx.x * 256 + threadIdx.x;
    if (i >= NALL4) return;
    const float* in;
    __half* out;
    int j = i;
    if (j < NX4)                 { in = X;  out = Xh;  }
    else if ((j -= NX4) < NW4)   { in = Wq; out = Wqh; }
    else if ((j -= NW4) < NW4)   { in = Wk; out = Wkh; }
    else { j -= NW4;               in = Wv; out = Wvh; }
    float4 v = reinterpret_cast<const float4*>(in)[j];
    __half2* o = reinterpret_cast<__half2*>(out) + j * 2;
    o[0] = __floats2half2_rn(v.x, v.y);
    o[1] = __floats2half2_rn(v.z, v.w);
}

// ---------------------------------------------------------------------------
// merge per-tile softmax partials -> scale table [B][NTILE][T]; reset ticket.
// One thread per (b, q) row; same arithmetic as the old PV prologue.
// ---------------------------------------------------------------------------
__global__ void __launch_bounds__(256)
scale_kernel(const float* __restrict__ pm, const float* __restrict__ pl,
             float* __restrict__ scl) {
    if (blockIdx.x == 0 && threadIdx.x == 0) g_ticket = 0;   // PV scheduler reset
    const int idx = blockIdx.x * 256 + threadIdx.x;
    if (idx >= BATCH * T) return;
    const int bz = idx / T, q = idx - bz * T;
    const int qt = q >> 7;
    const float* pmr = pm + (size_t)idx * NTILE;
    const float* plr = pl + (size_t)idx * NTILE;
    float m = -3.4e38f;
    for (int tx = 0; tx <= qt; tx++) m = fmaxf(m, pmr[tx]);
    float l = 0.f;
    for (int tx = 0; tx <= qt; tx++) l += plr[tx] * __expf(pmr[tx] - m);
    const float il = 1.f / l;
    for (int tx = 0; tx <= qt; tx++)
        scl[((size_t)bz * NTILE + tx) * T + q] = __expf(pmr[tx] - m) * il;
}

// ---------------------------------------------------------------------------
// launch
// ---------------------------------------------------------------------------
extern "C" void kernel_launch(void* const* d_in, const int* in_sizes, int n_in,
                              void* d_out, int out_size) {
    const float* X  = (const float*)d_in[0];
    const float* Wq = (const float*)d_in[1];
    const float* Wk = (const float*)d_in[2];
    const float* Wv = (const float*)d_in[3];
    float* out = (float*)d_out;

    __half *Xh, *Wqh, *Wkh, *Wvh, *Qp, *Kp, *Vtp, *Sp;
    float *pmp, *plp, *sclp;
    cudaGetSymbolAddress((void**)&Xh, g_Xh);
    cudaGetSymbolAddress((void**)&Wqh, g_Wq);
    cudaGetSymbolAddress((void**)&Wkh, g_Wk);
    cudaGetSymbolAddress((void**)&Wvh, g_Wv);
    cudaGetSymbolAddress((void**)&Qp, g_Q);
    cudaGetSymbolAddress((void**)&Kp, g_K);
    cudaGetSymbolAddress((void**)&Vtp, g_Vt);
    cudaGetSymbolAddress((void**)&Sp, g_S);
    cudaGetSymbolAddress((void**)&pmp, g_pm);
    cudaGetSymbolAddress((void**)&plp, g_pl);
    cudaGetSymbolAddress((void**)&sclp, g_scale);

    cudaFuncSetAttribute(tc_gemm<0>, cudaFuncAttributeMaxDynamicSharedMemorySize, SMEM_TOTAL);
    cudaFuncSetAttribute(tc_gemm<1>, cudaFuncAttributeMaxDynamicSharedMemorySize, SMEM_TOTAL);
    cudaFuncSetAttribute(tc_gemm<2>, cudaFuncAttributeMaxDynamicSharedMemorySize, SMEM_TOTAL);

    // fp16 operands: one merged launch
    cvt_all_kernel<<<(NALL4 + 255) / 256, 256>>>(X, Wq, Wk, Wv, Xh, Wqh, Wkh, Wvh);

    // QKV projections (persistent, static)
    tc_gemm<2><<<GRID_P, NT, SMEM_TOTAL>>>(
        Xh, Wqh, Wkh, Wvh, Qp, Kp, Vtp, nullptr, nullptr, nullptr,
        D, D, D, D, 0, 0, 0);

    // S tiles: P_t = exp(QK^T - m_tile) + partial stats (persistent, static)
    tc_gemm<0><<<GRID_P, NT, SMEM_TOTAL>>>(
        Qp, Kp, nullptr, nullptr, Sp, nullptr, nullptr, pmp, plp, nullptr,
        D, D, D, T,
        (long long)T * D, (long long)T * D, (long long)T * T);

    // merge partials -> scale table; reset PV ticket
    scale_kernel<<<(BATCH * T + 255) / 256, 256>>>(pmp, plp, sclp);

    // out = softmax(S) V  (persistent, DYNAMIC heavy-first, fused scaling)
    tc_gemm<1><<<GRID_P, NT, SMEM_TOTAL>>>(
        Sp, Vtp, nullptr, nullptr, out, nullptr, nullptr, pmp, plp, sclp,
        T, T, MQKV, D,
        (long long)T * T, (long long)T, (long long)T * D);
}

// round 16
// speedup vs baseline: 1.0700x; 1.0700x over previous
#include <cuda_runtime.h>
#include <cuda_fp16.h>
#include <cstdint>

// ---------------------------------------------------------------------------
// SelfAttention B=4, T=2048, D=1024, causal — fp16 persistent edition v6.
// R14 (best: 303.5us) + zero-cost static load balancing for PV:
//   heavy-order pairing — CTA i processes heavy-rank tiles {i, 511-i}.
//   Every paired CTA totals 34 kt (was: 46-kt straggler). No atomics,
//   no extra kernels (R15's dynamic-ticket + scale-kernel detour reverted:
//   it cost +8us of launch latency for no PV gain).
//   Proj: Q = Xh Wq^T / 32 ; K = Xh Wk^T ; Vt = (Xh Wv^T)^T   (fp16 outputs)
//   S-GEMM (live causal tiles): P_t = exp(S - m_tile) (fp16) + (m,l) partials
//   PV-GEMM: prologue merges partials; A fragments scaled via __hmul2.
// GEMM core: 128x128x(BK=64 fp16), 3-stage cp.async, XOR-swizzled smem,
// ldmatrix.x4.b16, m16n8k16 (f32 acc), 8 warps, 2 CTAs/SM, persistent 296.
// ---------------------------------------------------------------------------

namespace {
constexpr int BATCH = 4;
constexpr int T     = 2048;
constexpr int D     = 1024;
constexpr int MQKV  = BATCH * T;          // 8192
constexpr int NTILE = T / 128;            // 16

constexpr int BM = 128, BN = 128, BK = 64;   // BK fp16 = 128 B rows
constexpr int STG = 3;
constexpr int NT  = 256;                      // 8 warps
constexpr int GRID_P = 296;                   // persistent CTAs

constexpr int A_STG = BM * 128;               // 16384 B
constexpr int B_STG = BN * 128;               // 16384 B
constexpr int STG_BYTES = A_STG + B_STG;      // 32768 B
constexpr int SMEM_TOTAL = STG * STG_BYTES;   // 98304 B

constexpr int NT_S  = BATCH * (NTILE * (NTILE + 1) / 2);  // 544
constexpr int NT_PV = (D / BN) * NTILE * BATCH;           // 512
constexpr int NT_PJ = (D / BN) * (MQKV / BM) * 3;         // 1536

constexpr int TSTRIDE = 130;                  // transpose buffer stride (halves)

constexpr int NX4 = MQKV * D / 4;             // 2097152
constexpr int NW4 = D * D / 4;                // 262144
constexpr int NALL4 = NX4 + 3 * NW4;          // 2883584
}

// scratch (device globals — allocation-free)
__device__ __half g_Xh[(size_t)MQKV * D];
__device__ __half g_Wq[(size_t)D * D];
__device__ __half g_Wk[(size_t)D * D];
__device__ __half g_Wv[(size_t)D * D];
__device__ __half g_Q [(size_t)MQKV * D];
__device__ __half g_K [(size_t)MQKV * D];
__device__ __half g_Vt[(size_t)D * MQKV];                 // V transposed [D][B*T]
__device__ __half g_S [(size_t)BATCH * T * T];            // P_t (fp16)
__device__ float  g_pm[(size_t)BATCH * T * NTILE];
__device__ float  g_pl[(size_t)BATCH * T * NTILE];

// ---------------------------------------------------------------------------
// helpers
// ---------------------------------------------------------------------------
__device__ __forceinline__ uint32_t smem_u32(const void* p) {
    uint32_t a;
    asm("{ .reg .u64 t; cvta.to.shared.u64 t, %1; cvt.u32.u64 %0, t; }" : "=r"(a) : "l"(p));
    return a;
}
__device__ __forceinline__ void cp16s(uint32_t s, const void* g) {
    asm volatile("cp.async.cg.shared.global [%0], [%1], 16;" ::"r"(s), "l"(g));
}
__device__ __forceinline__ void cp_commit() { asm volatile("cp.async.commit_group;"); }
__device__ __forceinline__ void cp_wait1()  { asm volatile("cp.async.wait_group 1;"); }

__device__ __forceinline__ void ldsm4(uint32_t& r0, uint32_t& r1, uint32_t& r2,
                                      uint32_t& r3, uint32_t addr) {
    asm volatile("ldmatrix.sync.aligned.m8n8.x4.shared.b16 {%0,%1,%2,%3}, [%4];"
                 : "=r"(r0), "=r"(r1), "=r"(r2), "=r"(r3) : "r"(addr));
}
__device__ __forceinline__ void mma16(float* c, const uint32_t* a, const uint32_t* b) {
    asm volatile(
        "mma.sync.aligned.m16n8k16.row.col.f32.f16.f16.f32 "
        "{%0,%1,%2,%3}, {%4,%5,%6,%7}, {%8,%9}, {%0,%1,%2,%3};"
        : "+f"(c[0]), "+f"(c[1]), "+f"(c[2]), "+f"(c[3])
        : "r"(a[0]), "r"(a[1]), "r"(a[2]), "r"(a[3]), "r"(b[0]), "r"(b[1]));
}
__device__ __forceinline__ uint32_t hmul2u(uint32_t a, __half2 s) {
    __half2 h = *reinterpret_cast<__half2*>(&a);
    h = __hmul2(h, s);
    return *reinterpret_cast<uint32_t*>(&h);
}

// ---------------------------------------------------------------------------
// Persistent TN GEMM (fp16 operands, f32 acc):  C[m,n] = sum_k A[m,k] B[n,k]
//   MODE 0: S = QK^T over live causal tiles (static); exp+partials epilogue
//   MODE 1: out = softmax(S) V; paired heavy/light static schedule
//   MODE 2: QKV projection (static); bz==2 -> Vt via smem-staged transpose
// ---------------------------------------------------------------------------
template <int MODE>
__global__ void __launch_bounds__(NT, 2)
tc_gemm(const __half* __restrict__ A,
        const __half* __restrict__ B0, const __half* __restrict__ B1,
        const __half* __restrict__ B2,
        void* __restrict__ C0, void* __restrict__ C1, void* __restrict__ C2,
        float* __restrict__ pm, float* __restrict__ pl,
        int Kbase, int lda, int ldb, int ldc,
        long long sA, long long sB, long long sC) {
    extern __shared__ char smem[];
    const uint32_t sb = smem_u32(smem);
    __shared__ float red[4 * 128];               // MODE 0 reductions
    __shared__ float srow[128];
    __shared__ float saux[NTILE * 128];          // MODE 1 scale table

    const int tid = threadIdx.x, w = tid >> 5, lane = tid & 31;
    const int wm = w >> 2, wn = w & 3;           // 2 x 4 warps, 64x32 each

    const int cr = tid >> 3, cc = tid & 7;
    const uint32_t c_sw = (uint32_t)(cc * 16) ^ ((uint32_t)(cr & 7) << 4);

    const int l7 = lane & 7, lb3 = (lane >> 3) & 1, lb4 = (lane >> 4) & 1;
    const uint32_t xr = (uint32_t)l7 << 4;
    const uint32_t aRow0 = (uint32_t)(wm * 64 + lb3 * 8 + l7) * 128;
    const uint32_t aSeg  = (uint32_t)lb4 * 16;
    const uint32_t bRow0 = (uint32_t)(wn * 32 + lb4 * 8 + l7) * 128;
    const uint32_t bSeg  = (uint32_t)lb3 * 16;

    const int ntiles = (MODE == 0) ? NT_S : (MODE == 1) ? NT_PV : NT_PJ;

    const __half* Ab = nullptr;
    const __half* Bb = nullptr;

    auto ldst = [&](int slot, int kt) {
        const uint32_t stg = sb + slot * STG_BYTES;
        const __half* ag = Ab + kt * BK;
#pragma unroll
        for (int i = 0; i < 4; i++) {
            int r = cr + i * 32;
            cp16s(stg + (uint32_t)r * 128 + c_sw, ag + (size_t)r * lda + cc * 8);
        }
        const __half* bg = Bb + kt * BK;
#pragma unroll
        for (int i = 0; i < 4; i++) {
            int r = cr + i * 32;
            cp16s(stg + A_STG + (uint32_t)r * 128 + c_sw, bg + (size_t)r * ldb + cc * 8);
        }
    };

    int iter = 0;
    for (;;) {
        // ---- pick tile ----
        int t;
        if (MODE == 1) {
            // heavy-order pairing: CTA i -> heavy-rank {i, NT_PV-1-i}
            if (iter == 0) {
                t = blockIdx.x;
            } else if (iter == 1) {
                t = (NT_PV - 1) - (int)blockIdx.x;
                if (t < GRID_P) break;           // only CTAs 0..215 get a 2nd tile
            } else break;
        } else {
            t = blockIdx.x + iter * gridDim.x;
            if (t >= ntiles) break;
        }
        iter++;

        // ---- decode tile ----
        int bx, by, bz;
        if (MODE == 0) {
            bz = t / (NT_S / BATCH);
            int i0 = t % (NT_S / BATCH);
            int acc0 = 0; by = 0;
            while (i0 >= acc0 + by + 1) { acc0 += by + 1; by++; }
            bx = i0 - acc0;
        } else if (MODE == 1) {
            by = (NTILE - 1) - (t >> 5);         // heavy-rank decode
            int r = t & 31; bx = r & 7; bz = r >> 3;
        } else {
            bz = t >> 9; int r = t & 511; by = r >> 3; bx = r & 7;
        }

        const int K = (MODE == 1) ? (by + 1) * BM : Kbase;
        const int nkt = K / BK;

        const __half* Bsel = (MODE == 2) ? (bz == 0 ? B0 : bz == 1 ? B1 : B2) : B0;
        Ab = A + (size_t)bz * sA + (size_t)by * BM * lda;
        Bb = Bsel + (size_t)bz * sB + (size_t)bx * BN * ldb;

        ldst(0, 0); cp_commit();
        if (nkt > 1) ldst(1, 1);
        cp_commit();

        if (MODE == 1) {
            if (tid < 128) {
                const int q = by * BM + tid;
                const float* pmr = pm + ((size_t)bz * T + q) * NTILE;
                const float* plr = pl + ((size_t)bz * T + q) * NTILE;
                float m = -3.4e38f;
                for (int tx = 0; tx <= by; tx++) m = fmaxf(m, pmr[tx]);
                float l = 0.f;
                for (int tx = 0; tx <= by; tx++) l += plr[tx] * __expf(pmr[tx] - m);
                const float il = 1.f / l;
                for (int tx = 0; tx <= by; tx++)
                    saux[tx * 128 + tid] = __expf(pmr[tx] - m) * il;
            }
            __syncthreads();
        }

        float acc[4][4][4];
#pragma unroll
        for (int i = 0; i < 4; i++)
#pragma unroll
            for (int j = 0; j < 4; j++)
#pragma unroll
                for (int k = 0; k < 4; k++) acc[i][j][k] = 0.f;

        __half2 sc0[4], sc1[4];
        int slot = 0;
        for (int kt = 0; kt < nkt; kt++) {
            cp_wait1();
            __syncthreads();                      // single per-kt barrier
            if (kt + 2 < nkt) {
                int ns = slot + 2; if (ns >= STG) ns -= STG;
                ldst(ns, kt + 2);
            }
            cp_commit();

            if (MODE == 1 && (kt & 1) == 0) {
                const int tx = kt >> 1;
#pragma unroll
                for (int mi = 0; mi < 4; mi++) {
                    const int ar = wm * 64 + mi * 16 + (lane >> 2);
                    sc0[mi] = __float2half2_rn(saux[tx * 128 + ar]);
                    sc1[mi] = __float2half2_rn(saux[tx * 128 + ar + 8]);
                }
            }

            const uint32_t astg = sb + slot * STG_BYTES;
            const uint32_t bstg = astg + A_STG;
#pragma unroll
            for (int kk4 = 0; kk4 < 128; kk4 += 32) {
                uint32_t af[4][4], bf[4][2];
                const uint32_t aoff = ((uint32_t)kk4 | aSeg) ^ xr;
                const uint32_t boff = ((uint32_t)kk4 | bSeg) ^ xr;
#pragma unroll
                for (int mi = 0; mi < 4; mi++) {
                    ldsm4(af[mi][0], af[mi][1], af[mi][2], af[mi][3],
                          astg + aRow0 + (uint32_t)mi * 2048 + aoff);
                    if (MODE == 1) {
                        af[mi][0] = hmul2u(af[mi][0], sc0[mi]);
                        af[mi][2] = hmul2u(af[mi][2], sc0[mi]);
                        af[mi][1] = hmul2u(af[mi][1], sc1[mi]);
                        af[mi][3] = hmul2u(af[mi][3], sc1[mi]);
                    }
                }
#pragma unroll
                for (int nj = 0; nj < 2; nj++) {
                    uint32_t r0, r1, r2, r3;
                    ldsm4(r0, r1, r2, r3, bstg + bRow0 + (uint32_t)nj * 2048 + boff);
                    bf[nj * 2][0] = r0; bf[nj * 2][1] = r1;
                    bf[nj * 2 + 1][0] = r2; bf[nj * 2 + 1][1] = r3;
                }
#pragma unroll
                for (int mi = 0; mi < 4; mi++)
#pragma unroll
                    for (int ni = 0; ni < 4; ni++) mma16(acc[mi][ni], af[mi], bf[ni]);
            }
            if (++slot == STG) slot = 0;
        }
        __syncthreads();                          // all compute done; smem free

        // ---- MODE 0 epilogue: exp + stats ----
        if (MODE == 0) {
            const bool diag = (bx == by);
#pragma unroll
            for (int mi = 0; mi < 4; mi++) {
#pragma unroll
                for (int h = 0; h < 2; h++) {
                    const int r = wm * 64 + mi * 16 + (lane >> 2) + 8 * h;
                    float mx = -3.4e38f;
#pragma unroll
                    for (int ni = 0; ni < 4; ni++) {
#pragma unroll
                        for (int c2 = 0; c2 < 2; c2++) {
                            const int c = wn * 32 + ni * 8 + ((lane & 3) << 1) + c2;
                            const bool ok = !diag || (c <= r);
                            if (ok) mx = fmaxf(mx, acc[mi][ni][2 * h + c2]);
                        }
                    }
                    mx = fmaxf(mx, __shfl_xor_sync(0xffffffffu, mx, 1));
                    mx = fmaxf(mx, __shfl_xor_sync(0xffffffffu, mx, 2));
                    if ((lane & 3) == 0) red[wn * 128 + r] = mx;
                }
            }
            __syncthreads();
            if (tid < 128)
                srow[tid] = fmaxf(fmaxf(red[tid], red[128 + tid]),
                                  fmaxf(red[256 + tid], red[384 + tid]));
            __syncthreads();
#pragma unroll
            for (int mi = 0; mi < 4; mi++) {
#pragma unroll
                for (int h = 0; h < 2; h++) {
                    const int r = wm * 64 + mi * 16 + (lane >> 2) + 8 * h;
                    const float m = srow[r];
                    float sum = 0.f;
#pragma unroll
                    for (int ni = 0; ni < 4; ni++) {
#pragma unroll
                        for (int c2 = 0; c2 < 2; c2++) {
                            const int c = wn * 32 + ni * 8 + ((lane & 3) << 1) + c2;
                            const bool ok = !diag || (c <= r);
                            const float e = ok ? __expf(acc[mi][ni][2 * h + c2] - m) : 0.f;
                            acc[mi][ni][2 * h + c2] = e;
                            sum += e;
                        }
                    }
                    sum += __shfl_xor_sync(0xffffffffu, sum, 1);
                    sum += __shfl_xor_sync(0xffffffffu, sum, 2);
                    if ((lane & 3) == 0) red[wn * 128 + r] = sum;
                }
            }
            __syncthreads();
            if (tid < 128) {
                const float l = red[tid] + red[128 + tid] + red[256 + tid] + red[384 + tid];
                const int q = by * BM + tid;
                pm[((size_t)bz * T + q) * NTILE + bx] = srow[tid];
                pl[((size_t)bz * T + q) * NTILE + bx] = l;
            }
            __syncthreads();
        }

        // ---- store ----
        if (MODE == 2 && bz == 2) {
            __half* sT = reinterpret_cast<__half*>(smem);
#pragma unroll
            for (int mi = 0; mi < 4; mi++) {
#pragma unroll
                for (int ni = 0; ni < 4; ni++) {
                    const int r0 = wm * 64 + mi * 16 + (lane >> 2);
                    const int c0 = wn * 32 + ni * 8 + ((lane & 3) << 1);
                    sT[c0 * TSTRIDE + r0]           = __float2half_rn(acc[mi][ni][0]);
                    sT[(c0 + 1) * TSTRIDE + r0]     = __float2half_rn(acc[mi][ni][1]);
                    sT[c0 * TSTRIDE + r0 + 8]       = __float2half_rn(acc[mi][ni][2]);
                    sT[(c0 + 1) * TSTRIDE + r0 + 8] = __float2half_rn(acc[mi][ni][3]);
                }
            }
            __syncthreads();
            __half* Cv = (__half*)C2;
            const int gr0 = by * BM;
#pragma unroll
            for (int i = 0; i < 32; i++) {
                const int idx = tid + i * NT;
                const int c  = idx >> 6;
                const int rp = idx & 63;
                const __half2 hv = *reinterpret_cast<const __half2*>(
                    &sT[c * TSTRIDE + rp * 2]);
                *reinterpret_cast<__half2*>(
                    &Cv[(size_t)(bx * BN + c) * MQKV + gr0 + rp * 2]) = hv;
            }
            __syncthreads();
        } else {
#pragma unroll
            for (int mi = 0; mi < 4; mi++) {
#pragma unroll
                for (int ni = 0; ni < 4; ni++) {
                    const int row = by * BM + wm * 64 + mi * 16 + (lane >> 2);
                    const int col = bx * BN + wn * 32 + ni * 8 + ((lane & 3) << 1);
                    float v0 = acc[mi][ni][0], v1 = acc[mi][ni][1];
                    float v2 = acc[mi][ni][2], v3 = acc[mi][ni][3];
                    if (MODE == 2) {
                        if (bz == 0) { v0 *= 0.03125f; v1 *= 0.03125f; v2 *= 0.03125f; v3 *= 0.03125f; }
                        __half* Cd = (__half*)(bz == 0 ? C0 : C1);
                        *reinterpret_cast<__half2*>(Cd + (size_t)row * ldc + col) =
                            __floats2half2_rn(v0, v1);
                        *reinterpret_cast<__half2*>(Cd + (size_t)(row + 8) * ldc + col) =
                            __floats2half2_rn(v2, v3);
                    } else if (MODE == 0) {
                        __half* Cd = (__half*)C0 + (size_t)bz * sC;
                        *reinterpret_cast<__half2*>(Cd + (size_t)row * ldc + col) =
                            __floats2half2_rn(v0, v1);
                        *reinterpret_cast<__half2*>(Cd + (size_t)(row + 8) * ldc + col) =
                            __floats2half2_rn(v2, v3);
                    } else {
                        float* Cd = (float*)C0 + (size_t)bz * sC;
                        *reinterpret_cast<float2*>(Cd + (size_t)row * ldc + col) = make_float2(v0, v1);
                        *reinterpret_cast<float2*>(Cd + (size_t)(row + 8) * ldc + col) = make_float2(v2, v3);
                    }
                }
            }
        }
    }
}

// ---------------------------------------------------------------------------
// merged elementwise fp32 -> fp16 conversion for X, Wq, Wk, Wv (one launch)
// ---------------------------------------------------------------------------
__global__ void __launch_bounds__(256)
cvt_all_kernel(const float* __restrict__ X,  const float* __restrict__ Wq,
               const float* __restrict__ Wk, const float* __restrict__ Wv,
               __half* __restrict__ Xh,  __half* __restrict__ Wqh,
               __half* __restrict__ Wkh, __half* __restrict__ Wvh) {
    int i = blockIdx.x * 256 + threadIdx.x;
    if (i >= NALL4) return;
    const float* in;
    __half* out;
    int j = i;
    if (j < NX4)                 { in = X;  out = Xh;  }
    else if ((j -= NX4) < NW4)   { in = Wq; out = Wqh; }
    else if ((j -= NW4) < NW4)   { in = Wk; out = Wkh; }
    else { j -= NW4;               in = Wv; out = Wvh; }
    float4 v = reinterpret_cast<const float4*>(in)[j];
    __half2* o = reinterpret_cast<__half2*>(out) + j * 2;
    o[0] = __floats2half2_rn(v.x, v.y);
    o[1] = __floats2half2_rn(v.z, v.w);
}

// ---------------------------------------------------------------------------
// launch
// ---------------------------------------------------------------------------
extern "C" void kernel_launch(void* const* d_in, const int* in_sizes, int n_in,
                              void* d_out, int out_size) {
    const float* X  = (const float*)d_in[0];
    const float* Wq = (const float*)d_in[1];
    const float* Wk = (const float*)d_in[2];
    const float* Wv = (const float*)d_in[3];
    float* out = (float*)d_out;

    __half *Xh, *Wqh, *Wkh, *Wvh, *Qp, *Kp, *Vtp, *Sp;
    float *pmp, *plp;
    cudaGetSymbolAddress((void**)&Xh, g_Xh);
    cudaGetSymbolAddress((void**)&Wqh, g_Wq);
    cudaGetSymbolAddress((void**)&Wkh, g_Wk);
    cudaGetSymbolAddress((void**)&Wvh, g_Wv);
    cudaGetSymbolAddress((void**)&Qp, g_Q);
    cudaGetSymbolAddress((void**)&Kp, g_K);
    cudaGetSymbolAddress((void**)&Vtp, g_Vt);
    cudaGetSymbolAddress((void**)&Sp, g_S);
    cudaGetSymbolAddress((void**)&pmp, g_pm);
    cudaGetSymbolAddress((void**)&plp, g_pl);

    cudaFuncSetAttribute(tc_gemm<0>, cudaFuncAttributeMaxDynamicSharedMemorySize, SMEM_TOTAL);
    cudaFuncSetAttribute(tc_gemm<1>, cudaFuncAttributeMaxDynamicSharedMemorySize, SMEM_TOTAL);
    cudaFuncSetAttribute(tc_gemm<2>, cudaFuncAttributeMaxDynamicSharedMemorySize, SMEM_TOTAL);

    // fp16 operands: one merged launch
    cvt_all_kernel<<<(NALL4 + 255) / 256, 256>>>(X, Wq, Wk, Wv, Xh, Wqh, Wkh, Wvh);

    // QKV projections (persistent, static)
    tc_gemm<2><<<GRID_P, NT, SMEM_TOTAL>>>(
        Xh, Wqh, Wkh, Wvh, Qp, Kp, Vtp, nullptr, nullptr,
        D, D, D, D, 0, 0, 0);

    // S tiles: P_t = exp(QK^T - m_tile) + partial stats (persistent, static)
    tc_gemm<0><<<GRID_P, NT, SMEM_TOTAL>>>(
        Qp, Kp, nullptr, nullptr, Sp, nullptr, nullptr, pmp, plp,
        D, D, D, T,
        (long long)T * D, (long long)T * D, (long long)T * T);

    // out = softmax(S) V  (persistent, paired heavy/light schedule)
    tc_gemm<1><<<GRID_P, NT, SMEM_TOTAL>>>(
        Sp, Vtp, nullptr, nullptr, out, nullptr, nullptr, pmp, plp,
        T, T, MQKV, D,
        (long long)T * T, (long long)T, (long long)T * D);
}